// round 11
// baseline (speedup 1.0000x reference)
#include <cuda_runtime.h>
#include <cstddef>

// Involution (B=8, H=W=192, C=64, G=4, K=3, R=4 -> cr=16)
// R11: two-kernel split.
//  A) kerngen: per-pixel 1x1convs -> 3x3xG filter values, transposed scratch [36][pix]
//  B) apply:   halo tile + per-pixel 3x3 grouped filter (R10 phase D)

#define HH 192
#define WW 192
#define CC 64
#define CR 16
#define TAPS 9
#define NPIX (8 * HH * WW)   // 294912

// ---------------- global scratch / weights ----------------
__device__ float4 gW1[256];            // [c4=16][d=16], BN folded
__device__ float4 gW2[144];            // [d=16][tap=9], f4 over groups
struct ConstSmall { float4 b2[9]; float b1[16]; };
__constant__ ConstSmall cS;
__device__ ConstSmall scratchS;
__device__ float kscratch[36 * NPIX];  // transposed: [e][pix], 42.5 MB

// ---------------- prep ----------------
__global__ void involution_prep_kernel(const float* __restrict__ w1,
                                       const float* __restrict__ b1,
                                       const float* __restrict__ gamma,
                                       const float* __restrict__ beta,
                                       const float* __restrict__ mean,
                                       const float* __restrict__ var,
                                       const float* __restrict__ w2,
                                       const float* __restrict__ b2) {
    __shared__ float s[16];
    int tid = threadIdx.x;   // 256 threads
    if (tid < 16) {
        float sc = gamma[tid] * rsqrtf(var[tid] + 1e-3f);
        s[tid] = sc;
        scratchS.b1[tid] = (b1[tid] - mean[tid]) * sc + beta[tid];
    }
    __syncthreads();
    {
        int d  = tid & 15;
        int c4 = tid >> 4;
        float sc = s[d];
        gW1[tid] = make_float4(w1[(4 * c4 + 0) * CR + d] * sc,
                               w1[(4 * c4 + 1) * CR + d] * sc,
                               w1[(4 * c4 + 2) * CR + d] * sc,
                               w1[(4 * c4 + 3) * CR + d] * sc);
    }
    if (tid < 144) gW2[tid] = ((const float4*)w2)[tid];
    if (tid < 9)   scratchS.b2[tid] = ((const float4*)b2)[tid];
}

// ---------------- kernel A: kern generation ----------------
__global__ __launch_bounds__(256, 3)
void involution_kerngen_kernel(const float* __restrict__ x) {
    __shared__ float4 w1s[256];
    __shared__ float4 w2s[144];
    __shared__ float4 xst[2][256 * 5];     // [buf][px*5 + j], stride-5 pad

    const int tid = threadIdx.x;
    const size_t p0 = (size_t)blockIdx.x * 256;

    w1s[tid] = gW1[tid];
    if (tid < 144) w2s[tid] = gW2[tid];

    const float4* xg = (const float4*)x + p0 * 16;

    // stage chunk 0 (channels 0..15 = 4 f4 per pixel), coalesced
    #pragma unroll
    for (int i = tid; i < 1024; i += 256) {
        int px = i >> 2, j = i & 3;
        xst[0][px * 5 + j] = xg[(size_t)px * 16 + j];
    }
    __syncthreads();

    float t[CR];
    #pragma unroll
    for (int d = 0; d < CR; d++) t[d] = cS.b1[d];

    #pragma unroll
    for (int cc = 0; cc < 4; cc++) {
        int buf = cc & 1;
        if (cc < 3) {  // stage next chunk into the other buffer
            #pragma unroll
            for (int i = tid; i < 1024; i += 256) {
                int px = i >> 2, j = i & 3;
                xst[buf ^ 1][px * 5 + j] = xg[(size_t)px * 16 + (cc + 1) * 4 + j];
            }
        }
        #pragma unroll
        for (int j = 0; j < 4; j++) {
            float4 xv = xst[buf][tid * 5 + j];
            int c4 = cc * 4 + j;
            #pragma unroll
            for (int d = 0; d < CR; d++) {
                float4 w = w1s[c4 * 16 + d];
                t[d] = fmaf(xv.x, w.x, fmaf(xv.y, w.y, fmaf(xv.z, w.z, fmaf(xv.w, w.w, t[d]))));
            }
        }
        __syncthreads();
    }
    #pragma unroll
    for (int d = 0; d < CR; d++) t[d] = fmaxf(t[d], 0.f);

    // second 1x1 conv -> per-pixel filter k[tap] (f4 over 4 groups)
    float4 k[TAPS];
    #pragma unroll
    for (int tap = 0; tap < TAPS; tap++) k[tap] = cS.b2[tap];
    #pragma unroll
    for (int d = 0; d < CR; d++) {
        float a = t[d];
        #pragma unroll
        for (int tap = 0; tap < TAPS; tap++) {
            float4 w = w2s[d * TAPS + tap];
            k[tap].x = fmaf(a, w.x, k[tap].x);
            k[tap].y = fmaf(a, w.y, k[tap].y);
            k[tap].z = fmaf(a, w.z, k[tap].z);
            k[tap].w = fmaf(a, w.w, k[tap].w);
        }
    }

    // transposed store: kscratch[e][pix], e = tap*4 + g  -> 36 coalesced STG.32
    const size_t gp = p0 + tid;
    #pragma unroll
    for (int tap = 0; tap < TAPS; tap++) {
        kscratch[(size_t)(tap * 4 + 0) * NPIX + gp] = k[tap].x;
        kscratch[(size_t)(tap * 4 + 1) * NPIX + gp] = k[tap].y;
        kscratch[(size_t)(tap * 4 + 2) * NPIX + gp] = k[tap].z;
        kscratch[(size_t)(tap * 4 + 3) * NPIX + gp] = k[tap].w;
    }
}

// ---------------- kernel B: apply ----------------
constexpr int TILE = 16;
constexpr int HALO = 18;
constexpr int PSTR = 17;                              // f4 per pixel (16 + 1 pad)
constexpr int TILE_F4 = HALO * HALO * PSTR;           // 5508
constexpr int SMEM_BYTES = TILE_F4 * 16;              // 88128 B

__device__ __forceinline__ void fma4(float4& a, const float4& k, const float4& v) {
    a.x = fmaf(k.x, v.x, a.x);
    a.y = fmaf(k.y, v.y, a.y);
    a.z = fmaf(k.z, v.z, a.z);
    a.w = fmaf(k.w, v.w, a.w);
}

__device__ __forceinline__ void cp16(unsigned dst, const void* src, int sz) {
    asm volatile("cp.async.cg.shared.global [%0], [%1], 16, %2;"
                 :: "r"(dst), "l"(src), "r"(sz) : "memory");
}

__global__ __launch_bounds__(128)
void involution_apply_kernel(const float* __restrict__ x,
                             float* __restrict__ out) {
    extern __shared__ float4 tile4[];         // [18*18 px][17 f4]

    const int tid = threadIdx.x;              // 0..127
    const int tx  = tid & 15;
    const int tyy = tid >> 4;                 // 0..7 -> rows 2*tyy, 2*tyy+1
    const int gx0 = blockIdx.x * TILE;
    const int gy0 = blockIdx.y * TILE;
    const int bz  = blockIdx.z;

    const float* xb = x + (size_t)bz * ((size_t)HH * WW * CC);
    unsigned smem_base = (unsigned)__cvta_generic_to_shared(tile4);

    // full halo tile, branch-free cp.async with zero-fill
    #pragma unroll 4
    for (int s = tid; s < HALO * HALO * 16; s += 128) {
        int u   = s & 15;
        int pix = s >> 4;
        int py  = pix / HALO;
        int px  = pix - py * HALO;
        int gh  = gy0 - 1 + py;
        int gw  = gx0 - 1 + px;
        bool ok = ((unsigned)gh < HH) && ((unsigned)gw < WW);
        const float4* src = (const float4*)(xb + ((size_t)(ok ? gh : 0) * WW + (ok ? gw : 0)) * CC) + u;
        cp16(smem_base + (unsigned)(pix * PSTR + u) * 16u, src, ok ? 16 : 0);
    }
    asm volatile("cp.async.commit_group;" ::: "memory");

    // load this thread's two pixel filters (overlaps with cp.async)
    const size_t pix0 = ((size_t)bz * HH + gy0 + 2 * tyy) * WW + gx0 + tx;
    const size_t pix1 = pix0 + WW;
    float4 k0[TAPS], k1[TAPS];
    #pragma unroll
    for (int tap = 0; tap < TAPS; tap++) {
        k0[tap].x = kscratch[(size_t)(tap * 4 + 0) * NPIX + pix0];
        k0[tap].y = kscratch[(size_t)(tap * 4 + 1) * NPIX + pix0];
        k0[tap].z = kscratch[(size_t)(tap * 4 + 2) * NPIX + pix0];
        k0[tap].w = kscratch[(size_t)(tap * 4 + 3) * NPIX + pix0];
        k1[tap].x = kscratch[(size_t)(tap * 4 + 0) * NPIX + pix1];
        k1[tap].y = kscratch[(size_t)(tap * 4 + 1) * NPIX + pix1];
        k1[tap].z = kscratch[(size_t)(tap * 4 + 2) * NPIX + pix1];
        k1[tap].w = kscratch[(size_t)(tap * 4 + 3) * NPIX + pix1];
    }

    asm volatile("cp.async.wait_group 0;" ::: "memory");
    __syncthreads();

    // phase D: 4 smem rows serve 2 outputs
    float4* o0 = (float4*)(out + pix0 * CC);
    float4* o1 = (float4*)(out + pix1 * CC);
    const int rowstep = HALO * PSTR;
    const float4* base = tile4 + (2 * tyy * HALO + tx) * PSTR;

    #pragma unroll 4
    for (int u = 0; u < 16; u++) {
        float4 a0 = make_float4(0.f, 0.f, 0.f, 0.f);
        float4 a1 = make_float4(0.f, 0.f, 0.f, 0.f);
        #pragma unroll
        for (int dj = 0; dj < 3; dj++) {
            const float4* col = base + dj * PSTR + u;
            float4 r0 = col[0];
            float4 r1 = col[rowstep];
            float4 r2 = col[2 * rowstep];
            float4 r3 = col[3 * rowstep];
            fma4(a0, k0[dj],     r0);
            fma4(a0, k0[3 + dj], r1);
            fma4(a0, k0[6 + dj], r2);
            fma4(a1, k1[dj],     r1);
            fma4(a1, k1[3 + dj], r2);
            fma4(a1, k1[6 + dj], r3);
        }
        o0[u] = a0;
        o1[u] = a1;
    }
}

// ---------------- launch ----------------
extern "C" void kernel_launch(void* const* d_in, const int* in_sizes, int n_in,
                              void* d_out, int out_size) {
    const float* x     = (const float*)d_in[0];
    const float* w1    = (const float*)d_in[1];
    const float* b1    = (const float*)d_in[2];
    const float* gamma = (const float*)d_in[3];
    const float* beta  = (const float*)d_in[4];
    const float* mean  = (const float*)d_in[5];
    const float* var   = (const float*)d_in[6];
    const float* w2    = (const float*)d_in[7];
    const float* b2    = (const float*)d_in[8];
    float* out = (float*)d_out;

    int B = in_sizes[0] / (HH * WW * CC);
    int npix = B * HH * WW;

    // 1) fold BN + stage weights
    involution_prep_kernel<<<1, 256>>>(w1, b1, gamma, beta, mean, var, w2, b2);

    // 2) small constants -> __constant__ (D2D memcpy node, capturable)
    static void* sc_addr = nullptr;
    if (!sc_addr) cudaGetSymbolAddress(&sc_addr, scratchS);
    cudaMemcpyToSymbolAsync(cS, sc_addr, sizeof(ConstSmall), 0,
                            cudaMemcpyDeviceToDevice, 0);

    // 3) kernel A: filter generation
    involution_kerngen_kernel<<<npix / 256, 256>>>(x);

    // 4) kernel B: apply
    static bool attr_set = false;
    if (!attr_set) {
        cudaFuncSetAttribute(involution_apply_kernel,
                             cudaFuncAttributeMaxDynamicSharedMemorySize, SMEM_BYTES);
        attr_set = true;
    }
    dim3 grid(WW / TILE, HH / TILE, B);   // 12 x 12 x 8
    involution_apply_kernel<<<grid, 128, SMEM_BYTES>>>(x, out);
}

// round 12
// speedup vs baseline: 1.3336x; 1.3336x over previous
#include <cuda_runtime.h>
#include <cstddef>

// Involution (B=8, H=W=192, C=64, G=4, K=3, R=4 -> cr=16)
// R12: 128 thr/block, 32x16 tile, 4 VERTICAL px/thread, channel-split smem
// tile (8 f4/px, stride 9, 88KB, 2 blocks/SM), weights in __constant__,
// branch-free cp.async tile loads, 256-reg budget.

#define HH 192
#define WW 192
#define CC 64
#define CR 16
#define TAPS 9

constexpr int TW = 16;                                // tile width
constexpr int TH = 32;                                // tile height
constexpr int HW = 18;                                // halo width
constexpr int HT = 34;                                // halo height
constexpr int PSTR = 9;                               // f4 per pixel (8 data + 1 pad)
constexpr int TILE_F4 = HT * HW * PSTR;               // 5508
constexpr int SMEM_BYTES = TILE_F4 * 16;              // 88128 B

struct ConstW {
    float4 w1[256];   // [c4=16][d=16], BN folded
    float4 w2[144];   // [d=16][tap=9], f4 over 4 groups
    float4 b2[9];
    float  b1[16];    // BN-folded bias
};
__constant__ ConstW cW;
__device__ ConstW scratchW;

__global__ void involution_prep_kernel(const float* __restrict__ w1,
                                       const float* __restrict__ b1,
                                       const float* __restrict__ gamma,
                                       const float* __restrict__ beta,
                                       const float* __restrict__ mean,
                                       const float* __restrict__ var,
                                       const float* __restrict__ w2,
                                       const float* __restrict__ b2) {
    __shared__ float s[16];
    int tid = threadIdx.x;   // 256 threads
    if (tid < 16) {
        float sc = gamma[tid] * rsqrtf(var[tid] + 1e-3f);
        s[tid] = sc;
        scratchW.b1[tid] = (b1[tid] - mean[tid]) * sc + beta[tid];
    }
    __syncthreads();
    {
        int d  = tid & 15;
        int c4 = tid >> 4;
        float sc = s[d];
        scratchW.w1[tid] = make_float4(w1[(4 * c4 + 0) * CR + d] * sc,
                                       w1[(4 * c4 + 1) * CR + d] * sc,
                                       w1[(4 * c4 + 2) * CR + d] * sc,
                                       w1[(4 * c4 + 3) * CR + d] * sc);
    }
    if (tid < 144) scratchW.w2[tid] = ((const float4*)w2)[tid];
    if (tid < 9)   scratchW.b2[tid] = ((const float4*)b2)[tid];
}

__device__ __forceinline__ void fma4(float4& a, const float4& k, const float4& v) {
    a.x = fmaf(k.x, v.x, a.x);
    a.y = fmaf(k.y, v.y, a.y);
    a.z = fmaf(k.z, v.z, a.z);
    a.w = fmaf(k.w, v.w, a.w);
}

__device__ __forceinline__ void cp16(unsigned dst, const void* src, int sz) {
    asm volatile("cp.async.cg.shared.global [%0], [%1], 16, %2;"
                 :: "r"(dst), "l"(src), "r"(sz) : "memory");
}

// load one channel-half (u base = uh*8) of the 34x18 halo tile, zero-fill OOB
__device__ __forceinline__ void load_tile_half(unsigned smem_base,
                                               const float* __restrict__ xb,
                                               int gy0, int gx0, int uoff, int tid) {
    for (int s = tid; s < HT * HW * 8; s += 128) {
        int u   = s & 7;
        int pix = s >> 3;
        int py  = pix / HW;
        int px  = pix - py * HW;
        int gh  = gy0 - 1 + py;
        int gw  = gx0 - 1 + px;
        bool ok = ((unsigned)gh < HH) && ((unsigned)gw < WW);
        const float4* src = (const float4*)(xb + ((size_t)(ok ? gh : 0) * WW + (ok ? gw : 0)) * CC)
                            + uoff + u;
        cp16(smem_base + (unsigned)(pix * PSTR + u) * 16u, src, ok ? 16 : 0);
    }
    asm volatile("cp.async.commit_group;\n\tcp.async.wait_group 0;" ::: "memory");
}

__global__ __launch_bounds__(128, 2)
void involution_fused_kernel(const float* __restrict__ x,
                             float* __restrict__ out) {
    extern __shared__ float4 tile4[];         // [34*18 px][9 f4]

    const int tid = threadIdx.x;              // 0..127
    const int tx  = tid & 15;
    const int qy  = tid >> 4;                 // 0..7 -> output rows 4qy..4qy+3
    const int gx0 = blockIdx.x * TW;
    const int gy0 = blockIdx.y * TH;
    const int bz  = blockIdx.z;

    const float* xb = x + (size_t)bz * ((size_t)HH * WW * CC);
    unsigned smem_base = (unsigned)__cvta_generic_to_shared(tile4);

    // ---- tile half u0-7 ----
    load_tile_half(smem_base, xb, gy0, gx0, 0, tid);
    __syncthreads();

    // ---- phase B: t[p][d] = relu(x_p . w1' + b1'), 4 vertical pixels ----
    const float4* xc[4];
    const float4* gp[4];
    #pragma unroll
    for (int p = 0; p < 4; p++) {
        xc[p] = tile4 + ((4 * qy + p + 1) * HW + (tx + 1)) * PSTR;
        gp[p] = (const float4*)(xb + ((size_t)(gy0 + 4 * qy + p) * WW + gx0 + tx) * CC);
    }

    float t[4][CR];
    #pragma unroll
    for (int d = 0; d < CR; d++) {
        float b = cW.b1[d];
        t[0][d] = b; t[1][d] = b; t[2][d] = b; t[3][d] = b;
    }

    #pragma unroll 2
    for (int c4 = 0; c4 < 8; c4++) {               // first channel half from smem
        float4 xv0 = xc[0][c4], xv1 = xc[1][c4], xv2 = xc[2][c4], xv3 = xc[3][c4];
        #pragma unroll
        for (int d = 0; d < CR; d++) {
            float4 w = cW.w1[c4 * 16 + d];
            t[0][d] = fmaf(xv0.x, w.x, fmaf(xv0.y, w.y, fmaf(xv0.z, w.z, fmaf(xv0.w, w.w, t[0][d]))));
            t[1][d] = fmaf(xv1.x, w.x, fmaf(xv1.y, w.y, fmaf(xv1.z, w.z, fmaf(xv1.w, w.w, t[1][d]))));
            t[2][d] = fmaf(xv2.x, w.x, fmaf(xv2.y, w.y, fmaf(xv2.z, w.z, fmaf(xv2.w, w.w, t[2][d]))));
            t[3][d] = fmaf(xv3.x, w.x, fmaf(xv3.y, w.y, fmaf(xv3.z, w.z, fmaf(xv3.w, w.w, t[3][d]))));
        }
    }
    #pragma unroll 2
    for (int c4 = 8; c4 < 16; c4++) {              // second channel half from global
        float4 xv0 = gp[0][c4], xv1 = gp[1][c4], xv2 = gp[2][c4], xv3 = gp[3][c4];
        #pragma unroll
        for (int d = 0; d < CR; d++) {
            float4 w = cW.w1[c4 * 16 + d];
            t[0][d] = fmaf(xv0.x, w.x, fmaf(xv0.y, w.y, fmaf(xv0.z, w.z, fmaf(xv0.w, w.w, t[0][d]))));
            t[1][d] = fmaf(xv1.x, w.x, fmaf(xv1.y, w.y, fmaf(xv1.z, w.z, fmaf(xv1.w, w.w, t[1][d]))));
            t[2][d] = fmaf(xv2.x, w.x, fmaf(xv2.y, w.y, fmaf(xv2.z, w.z, fmaf(xv2.w, w.w, t[2][d]))));
            t[3][d] = fmaf(xv3.x, w.x, fmaf(xv3.y, w.y, fmaf(xv3.z, w.z, fmaf(xv3.w, w.w, t[3][d]))));
        }
    }
    #pragma unroll
    for (int d = 0; d < CR; d++) {
        t[0][d] = fmaxf(t[0][d], 0.f);
        t[1][d] = fmaxf(t[1][d], 0.f);
        t[2][d] = fmaxf(t[2][d], 0.f);
        t[3][d] = fmaxf(t[3][d], 0.f);
    }

    // ---- phase C: per-pixel 3x3 kernels (f4 over groups), weights x4 amortized ----
    float4 k[4][TAPS];
    #pragma unroll
    for (int tap = 0; tap < TAPS; tap++) {
        float4 b = cW.b2[tap];
        k[0][tap] = b; k[1][tap] = b; k[2][tap] = b; k[3][tap] = b;
    }
    #pragma unroll
    for (int d = 0; d < CR; d++) {
        float a0 = t[0][d], a1 = t[1][d], a2 = t[2][d], a3 = t[3][d];
        #pragma unroll
        for (int tap = 0; tap < TAPS; tap++) {
            float4 w = cW.w2[d * TAPS + tap];
            k[0][tap].x = fmaf(a0, w.x, k[0][tap].x); k[0][tap].y = fmaf(a0, w.y, k[0][tap].y);
            k[0][tap].z = fmaf(a0, w.z, k[0][tap].z); k[0][tap].w = fmaf(a0, w.w, k[0][tap].w);
            k[1][tap].x = fmaf(a1, w.x, k[1][tap].x); k[1][tap].y = fmaf(a1, w.y, k[1][tap].y);
            k[1][tap].z = fmaf(a1, w.z, k[1][tap].z); k[1][tap].w = fmaf(a1, w.w, k[1][tap].w);
            k[2][tap].x = fmaf(a2, w.x, k[2][tap].x); k[2][tap].y = fmaf(a2, w.y, k[2][tap].y);
            k[2][tap].z = fmaf(a2, w.z, k[2][tap].z); k[2][tap].w = fmaf(a2, w.w, k[2][tap].w);
            k[3][tap].x = fmaf(a3, w.x, k[3][tap].x); k[3][tap].y = fmaf(a3, w.y, k[3][tap].y);
            k[3][tap].z = fmaf(a3, w.z, k[3][tap].z); k[3][tap].w = fmaf(a3, w.w, k[3][tap].w);
        }
    }

    // ---- phase D: two channel-half passes; 6 smem rows serve 4 outputs ----
    float4* o[4];
    #pragma unroll
    for (int p = 0; p < 4; p++)
        o[p] = (float4*)(out + (((size_t)bz * HH + gy0 + 4 * qy + p) * WW + gx0 + tx) * CC);
    const int rowstep = HW * PSTR;
    const float4* base = tile4 + (4 * qy * HW + tx) * PSTR;

    #pragma unroll
    for (int uh = 0; uh < 2; uh++) {
        if (uh) {
            __syncthreads();
            load_tile_half(smem_base, xb, gy0, gx0, 8, tid);
            __syncthreads();
        }
        #pragma unroll 2
        for (int u = 0; u < 8; u++) {
            float4 a0 = make_float4(0.f, 0.f, 0.f, 0.f);
            float4 a1 = make_float4(0.f, 0.f, 0.f, 0.f);
            float4 a2 = make_float4(0.f, 0.f, 0.f, 0.f);
            float4 a3 = make_float4(0.f, 0.f, 0.f, 0.f);
            #pragma unroll
            for (int dj = 0; dj < 3; dj++) {
                const float4* col = base + dj * PSTR + u;
                float4 r0 = col[0];
                float4 r1 = col[rowstep];
                float4 r2 = col[2 * rowstep];
                float4 r3 = col[3 * rowstep];
                float4 r4 = col[4 * rowstep];
                float4 r5 = col[5 * rowstep];
                fma4(a0, k[0][dj],     r0);
                fma4(a0, k[0][3 + dj], r1);
                fma4(a0, k[0][6 + dj], r2);
                fma4(a1, k[1][dj],     r1);
                fma4(a1, k[1][3 + dj], r2);
                fma4(a1, k[1][6 + dj], r3);
                fma4(a2, k[2][dj],     r2);
                fma4(a2, k[2][3 + dj], r3);
                fma4(a2, k[2][6 + dj], r4);
                fma4(a3, k[3][dj],     r3);
                fma4(a3, k[3][3 + dj], r4);
                fma4(a3, k[3][6 + dj], r5);
            }
            o[0][uh * 8 + u] = a0;
            o[1][uh * 8 + u] = a1;
            o[2][uh * 8 + u] = a2;
            o[3][uh * 8 + u] = a3;
        }
    }
}

extern "C" void kernel_launch(void* const* d_in, const int* in_sizes, int n_in,
                              void* d_out, int out_size) {
    const float* x     = (const float*)d_in[0];
    const float* w1    = (const float*)d_in[1];
    const float* b1    = (const float*)d_in[2];
    const float* gamma = (const float*)d_in[3];
    const float* beta  = (const float*)d_in[4];
    const float* mean  = (const float*)d_in[5];
    const float* var   = (const float*)d_in[6];
    const float* w2    = (const float*)d_in[7];
    const float* b2    = (const float*)d_in[8];
    float* out = (float*)d_out;

    int B = in_sizes[0] / (HH * WW * CC);

    // 1) fold BN + stage weights
    involution_prep_kernel<<<1, 256>>>(w1, b1, gamma, beta, mean, var, w2, b2);

    // 2) copy into __constant__ (D2D memcpy node, graph-capturable)
    static void* scratch_addr = nullptr;
    if (!scratch_addr) cudaGetSymbolAddress(&scratch_addr, scratchW);
    cudaMemcpyToSymbolAsync(cW, scratch_addr, sizeof(ConstW), 0,
                            cudaMemcpyDeviceToDevice, 0);

    // 3) main fused kernel
    static bool attr_set = false;
    if (!attr_set) {
        cudaFuncSetAttribute(involution_fused_kernel,
                             cudaFuncAttributeMaxDynamicSharedMemorySize, SMEM_BYTES);
        attr_set = true;
    }
    dim3 grid(WW / TW, HH / TH, B);   // 12 x 6 x 8
    involution_fused_kernel<<<grid, 128, SMEM_BYTES>>>(x, out);
}